// round 13
// baseline (speedup 1.0000x reference)
#include <cuda_runtime.h>
#include <cuda_fp16.h>
#include <cstdint>

#define B_    16384
#define DIN_  1024
#define H_    512
#define DOUT_ 256
#define E_    8
#define NMID_ 2
#define EPS_  1e-5f

// ---------------- scratch (device globals: no allocs allowed) ----------------
__device__ __half g_xh[B_ * DIN_];      // split x; reused as mid-1 output
__device__ __half g_xl[B_ * DIN_];
__device__ __half g_ah[B_ * H_];        // start output
__device__ __half g_al[B_ * H_];
__device__ __half g_bh[B_ * H_];        // mid-0 output
__device__ __half g_bl[B_ * H_];
__device__ __half g_wh[E_ * H_ * H_];   // prepped weights [e][n][k]
__device__ __half g_wl[E_ * H_ * H_];
__device__ float  g_bias2[E_ * H_];
__device__ float  g_part_sum[32][H_];
__device__ float  g_part_sq[32][H_];
__device__ float  g_scale[H_];
__device__ float  g_shift[H_];
__device__ int    g_act[B_];
__device__ int    g_cnt[E_];
__device__ int    g_off[E_];
__device__ int    g_pos[E_];
__device__ int    g_perm[B_];

__device__ __forceinline__ void mma_f16(float* c, const uint32_t* a, const uint32_t* b) {
    asm volatile(
        "mma.sync.aligned.m16n8k16.row.col.f32.f16.f16.f32 "
        "{%0,%1,%2,%3}, {%4,%5,%6,%7}, {%8,%9}, {%0,%1,%2,%3};"
        : "+f"(c[0]), "+f"(c[1]), "+f"(c[2]), "+f"(c[3])
        : "r"(a[0]), "r"(a[1]), "r"(a[2]), "r"(a[3]), "r"(b[0]), "r"(b[1]));
}
__device__ __forceinline__ void ldsm4(uint32_t* r, uint32_t saddr) {
    asm volatile("ldmatrix.sync.aligned.m8n8.x4.shared.b16 {%0,%1,%2,%3}, [%4];"
                 : "=r"(r[0]), "=r"(r[1]), "=r"(r[2]), "=r"(r[3]) : "r"(saddr));
}
__device__ __forceinline__ void cpa16(uint32_t dst, const void* src) {
    asm volatile("cp.async.cg.shared.global [%0], [%1], 16;" :: "r"(dst), "l"(src));
}
__device__ __forceinline__ void cpa_commit() {
    asm volatile("cp.async.commit_group;" ::: "memory");
}
__device__ __forceinline__ void cpa_wait1() {
    asm volatile("cp.async.wait_group 1;" ::: "memory");
}
__device__ __forceinline__ void cpa_wait0() {
    asm volatile("cp.async.wait_group 0;" ::: "memory");
}

// SMEM: per stage: Ah | Al | Bh | Bl, each 128 rows x 80B (32 fp16 + 16B pad)
#define ROWB_    80
#define PART_B   (128 * ROWB_)          // 10240 B
#define BUFF_B   (4 * PART_B)           // 40960 B per stage
#define SMEM_BYTES (2 * BUFF_B)         // 81920 B

// ============ 3xFP16-split mma.sync GEMM (pre-split operands, cp.async) ============
// C = relu(A @ W^T + bias). A pre-split hi/lo fp16 [*,KK]; W pre-split+transposed
// [e][n][KK]. CTA tile 128x128, BK=32, 8 warps, warp tile 64x32.
template<int KK, bool EXPERT, bool FP16OUT>
__global__ __launch_bounds__(256, 2) void mma_gemm(
    const __half* __restrict__ Agh, const __half* __restrict__ Agl,
    const __half* __restrict__ Wgh, const __half* __restrict__ Wgl,
    const float* __restrict__ biasAll,
    __half* __restrict__ Ch, __half* __restrict__ Cl,
    float* __restrict__ Cf, int ldc)
{
    constexpr int NC = KK / 32;
    extern __shared__ __half smh[];

    const int tid  = threadIdx.x;
    const int wid  = tid >> 5;
    const int lane = tid & 31;
    const int gid  = lane >> 2;
    const int tig  = lane & 3;
    const int bm   = blockIdx.y * 128;
    const int bn0  = blockIdx.x * 128;

    int cnt = B_, pbase = 0;
    const __half* Wph = Wgh;
    const __half* Wpl = Wgl;
    const float* bias = biasAll;
    if (EXPERT) {
        const int e = blockIdx.z;
        cnt = g_cnt[e];
        if (bm >= cnt) return;
        pbase = g_off[e];
        Wph   = Wgh + (size_t)e * H_ * H_;
        Wpl   = Wgl + (size_t)e * H_ * H_;
        bias  = biasAll + (size_t)e * H_;
    }

    // ---- cp.async fill assignment: thread -> (row crow, 16B quarter cq) ----
    const int crow = tid >> 2, cq = tid & 3;
    int gr0 = bm + crow, gr1 = bm + crow + 64;
    if (EXPERT) {
        gr0 = g_perm[pbase + (gr0 < cnt ? gr0 : cnt - 1)];
        gr1 = g_perm[pbase + (bm + crow + 64 < cnt ? bm + crow + 64 : cnt - 1)];
    }
    const __half* sa0h = Agh + (size_t)gr0 * KK + cq * 8;
    const __half* sa0l = Agl + (size_t)gr0 * KK + cq * 8;
    const __half* sa1h = Agh + (size_t)gr1 * KK + cq * 8;
    const __half* sa1l = Agl + (size_t)gr1 * KK + cq * 8;
    const __half* sb0h = Wph + (size_t)(bn0 + crow) * KK + cq * 8;
    const __half* sb0l = Wpl + (size_t)(bn0 + crow) * KK + cq * 8;
    const __half* sb1h = sb0h + (size_t)64 * KK;
    const __half* sb1l = sb0l + (size_t)64 * KK;

    const uint32_t sbase = (uint32_t)__cvta_generic_to_shared(smh);
    const uint32_t d0 = (uint32_t)(crow * ROWB_ + cq * 16);
    const uint32_t d1 = d0 + 64 * ROWB_;

    auto fill = [&](int st, int c) {
        const uint32_t s = sbase + st * BUFF_B;
        const int ko = c * 32;
        cpa16(s + d0,              sa0h + ko);
        cpa16(s + d1,              sa1h + ko);
        cpa16(s + PART_B + d0,     sa0l + ko);
        cpa16(s + PART_B + d1,     sa1l + ko);
        cpa16(s + 2 * PART_B + d0, sb0h + ko);
        cpa16(s + 2 * PART_B + d1, sb1h + ko);
        cpa16(s + 3 * PART_B + d0, sb0l + ko);
        cpa16(s + 3 * PART_B + d1, sb1l + ko);
    };

    // ---- accumulators & ldmatrix addressing (identical to round-10 layout) ----
    float acc[4][4][4] = {};
    const int mbase = (wid & 1) * 64;
    const int nbase = (wid >> 1) * 32;
    const uint32_t aLane = (uint32_t)((mbase + (lane & 15)) * ROWB_ + (lane >> 4) * 16);
    const uint32_t bLane = (uint32_t)((nbase + (((lane >> 3) >> 1) * 8) + (lane & 7)) * ROWB_
                                      + ((lane >> 3) & 1) * 16);

    auto domma = [&](int buf) {
        const uint32_t aH = sbase + buf * BUFF_B + aLane;
        const uint32_t aL = aH + PART_B;
        const uint32_t bH = sbase + buf * BUFF_B + 2 * PART_B + bLane;
        const uint32_t bL = bH + PART_B;
#pragma unroll
        for (int ks = 0; ks < 2; ks++) {
            uint32_t bh[2][4], bl[2][4];
#pragma unroll
            for (int ntp = 0; ntp < 2; ntp++) {
                const uint32_t off = (uint32_t)(ntp * 16 * ROWB_ + ks * 32);
                ldsm4(bh[ntp], bH + off);
                ldsm4(bl[ntp], bL + off);
            }
#pragma unroll
            for (int mt = 0; mt < 4; mt++) {
                uint32_t ah[4], al[4];
                const uint32_t off = (uint32_t)(mt * 16 * ROWB_ + ks * 32);
                ldsm4(ah, aH + off);
                ldsm4(al, aL + off);
#pragma unroll
                for (int nt = 0; nt < 4; nt++) {
                    const uint32_t* bhp = &bh[nt >> 1][(nt & 1) * 2];
                    const uint32_t* blp = &bl[nt >> 1][(nt & 1) * 2];
                    mma_f16(acc[mt][nt], ah, bhp);
                    mma_f16(acc[mt][nt], ah, blp);
                    mma_f16(acc[mt][nt], al, bhp);
                }
            }
        }
    };

    // ---- async pipeline ----
    fill(0, 0); cpa_commit();
    fill(1, 1); cpa_commit();
    for (int c = 0; c < NC; c++) {
        if (c + 2 < NC) cpa_wait1(); else cpa_wait0();
        __syncthreads();
        domma(c & 1);
        __syncthreads();
        if (c + 2 < NC) { fill(c & 1, c + 2); cpa_commit(); }
    }

    // ---- epilogue: bias + relu ----
#pragma unroll
    for (int mt = 0; mt < 4; mt++) {
#pragma unroll
        for (int half = 0; half < 2; half++) {
            const int lrow = mbase + mt * 16 + gid + half * 8;   // tile-local 0..127
            bool valid = true;
            int orow = bm + lrow;
            if (EXPERT) {
                valid = (bm + lrow) < cnt;
                orow  = valid ? g_perm[pbase + bm + lrow] : 0;
            }
            if (!valid) continue;
#pragma unroll
            for (int nt = 0; nt < 4; nt++) {
                const int n = nbase + nt * 8 + tig * 2;
                const float2 bv = *(const float2*)(bias + bn0 + n);
                const float ox = fmaxf(acc[mt][nt][half * 2 + 0] + bv.x, 0.f);
                const float oy = fmaxf(acc[mt][nt][half * 2 + 1] + bv.y, 0.f);
                if (FP16OUT) {
                    const __half hx = __float2half_rn(ox);
                    const __half hy = __float2half_rn(oy);
                    const __half lx = __float2half_rn(ox - __half2float(hx));
                    const __half ly = __float2half_rn(oy - __half2float(hy));
                    *(__half2*)(Ch + (size_t)orow * ldc + bn0 + n) = __halves2half2(hx, hy);
                    *(__half2*)(Cl + (size_t)orow * ldc + bn0 + n) = __halves2half2(lx, ly);
                } else {
                    float2 o; o.x = ox; o.y = oy;
                    *(float2*)(Cf + (size_t)orow * ldc + bn0 + n) = o;
                }
            }
        }
    }
}

// ---------------- split x into hi/lo fp16 ----------------
__global__ void split_x(const float* __restrict__ x,
                        __half* __restrict__ xh, __half* __restrict__ xl)
{
    const int idx = (blockIdx.x * 256 + threadIdx.x) * 4;
    const float4 v = *(const float4*)(x + idx);
    __half h[4], l[4];
    const float vv[4] = { v.x, v.y, v.z, v.w };
#pragma unroll
    for (int q = 0; q < 4; q++) {
        h[q] = __float2half_rn(vv[q]);
        l[q] = __float2half_rn(vv[q] - __half2float(h[q]));
    }
    *(__half2*)(xh + idx)     = __halves2half2(h[0], h[1]);
    *(__half2*)(xh + idx + 2) = __halves2half2(h[2], h[3]);
    *(__half2*)(xl + idx)     = __halves2half2(l[0], l[1]);
    *(__half2*)(xl + idx + 2) = __halves2half2(l[2], l[3]);
}

// ---------------- weight prep: transpose + BN fold + split + bias fold --------
// src W [e][K][N] fp32 -> Wh/Wl [e][N][K] fp16 (W' = s_k * W), bias' = bias + t @ W.
// grid: (N/32, n_experts), block 256.
template<int K>
__global__ void prep_w(const float* __restrict__ W,
                       const float* __restrict__ bias_in,
                       const float* __restrict__ s, const float* __restrict__ t,
                       __half* __restrict__ Wh, __half* __restrict__ Wl,
                       float* __restrict__ bias_out, int N)
{
    __shared__ float tile[32][33];
    __shared__ float svec[32], tvec[32];
    const int e  = blockIdx.y;
    const int n0 = blockIdx.x * 32;
    const int tid = threadIdx.x;
    const int tx = tid & 31, ty = tid >> 5;           // read mapping
    const int wn = tid >> 3, wk = tid & 7;            // write mapping
    const float* Wsrc = W + (size_t)e * K * N;
    __half* Whd = Wh + (size_t)e * (size_t)N * K;
    __half* Wld = Wl + (size_t)e * (size_t)N * K;

    float oacc = 0.f;
    for (int kt = 0; kt < K / 32; kt++) {
        __syncthreads();
#pragma unroll
        for (int r = 0; r < 4; r++)
            tile[ty + r * 8][tx] = Wsrc[(size_t)(kt * 32 + ty + r * 8) * N + n0 + tx];
        if (ty == 0) {
            svec[tx] = s ? s[kt * 32 + tx] : 1.f;
            tvec[tx] = t ? t[kt * 32 + tx] : 0.f;
        }
        __syncthreads();
        __half h4[4], l4[4];
#pragma unroll
        for (int j = 0; j < 4; j++) {
            const int kl = wk * 4 + j;
            const float w0 = tile[kl][wn];
            const float w  = w0 * svec[kl];
            h4[j] = __float2half_rn(w);
            l4[j] = __float2half_rn(w - __half2float(h4[j]));
            oacc += tvec[kl] * w0;
        }
        __half* dh = Whd + (size_t)(n0 + wn) * K + kt * 32 + wk * 4;
        __half* dl = Wld + (size_t)(n0 + wn) * K + kt * 32 + wk * 4;
        *(__half2*)(dh)     = __halves2half2(h4[0], h4[1]);
        *(__half2*)(dh + 2) = __halves2half2(h4[2], h4[3]);
        *(__half2*)(dl)     = __halves2half2(l4[0], l4[1]);
        *(__half2*)(dl + 2) = __halves2half2(l4[2], l4[3]);
    }
#pragma unroll
    for (int o = 4; o; o >>= 1) oacc += __shfl_down_sync(0xffffffffu, oacc, o);
    if (wk == 0)
        bias_out[(size_t)e * N + n0 + wn] = bias_in[(size_t)e * N + n0 + wn] + oacc;
}

// ---------------- BN stats on hi/lo pairs (deterministic 2-stage) -------------
__global__ void mlnn_bn_stats(const __half* __restrict__ hh,
                              const __half* __restrict__ hl)
{
    __shared__ float s0[8][33], s1[8][33], q0[8][33], q1[8][33];
    const int tx = threadIdx.x, ty = threadIdx.y;
    const int c2 = blockIdx.x * 32 + tx;              // half2 column index
    const int r0 = blockIdx.y * 512;
    float a0 = 0.f, a1 = 0.f, b0 = 0.f, b1 = 0.f;
    for (int i = ty; i < 512; i += 8) {
        const __half2 vh = *(const __half2*)(hh + (size_t)(r0 + i) * H_ + 2 * c2);
        const __half2 vl = *(const __half2*)(hl + (size_t)(r0 + i) * H_ + 2 * c2);
        const float2 fh = __half22float2(vh);
        const float2 fl = __half22float2(vl);
        const float v0 = fh.x + fl.x, v1 = fh.y + fl.y;
        a0 += v0; b0 += v0 * v0;
        a1 += v1; b1 += v1 * v1;
    }
    s0[ty][tx] = a0; s1[ty][tx] = a1; q0[ty][tx] = b0; q1[ty][tx] = b1;
    __syncthreads();
    if (ty == 0) {
#pragma unroll
        for (int y = 1; y < 8; y++) {
            a0 += s0[y][tx]; a1 += s1[y][tx];
            b0 += q0[y][tx]; b1 += q1[y][tx];
        }
        g_part_sum[blockIdx.y][2 * c2]     = a0;
        g_part_sum[blockIdx.y][2 * c2 + 1] = a1;
        g_part_sq[blockIdx.y][2 * c2]      = b0;
        g_part_sq[blockIdx.y][2 * c2 + 1]  = b1;
    }
}

__global__ void mlnn_bn_finalize(const float* __restrict__ gamma,
                                 const float* __restrict__ beta)
{
    const int c = blockIdx.x * 256 + threadIdx.x;
    float s = 0.f, q = 0.f;
#pragma unroll
    for (int p = 0; p < 32; p++) { s += g_part_sum[p][c]; q += g_part_sq[p][c]; }
    const float m   = s * (1.f / B_);
    const float var = q * (1.f / B_) - m * m;
    const float sc  = gamma[c] / sqrtf(var + EPS_);
    g_scale[c] = sc;
    g_shift[c] = beta[c] - m * sc;
    if (blockIdx.x == 0 && threadIdx.x < E_) g_cnt[threadIdx.x] = 0;
}

// ---------------- routing: warp per row, BN fused, hi/lo reconstruct ---------
__global__ __launch_bounds__(256)
void mlnn_routing(const __half* __restrict__ hh, const __half* __restrict__ hl,
                  const float* __restrict__ W,    // [H,E]
                  const float* __restrict__ b)    // [E]
{
    __shared__ float Wt[E_ * H_];
    const int tid = threadIdx.x;
    for (int i = tid; i < H_ * E_; i += 256) {
        const int k = i >> 3, e = i & 7;
        Wt[e * H_ + k] = W[i];
    }
    __syncthreads();
    const int warp = tid >> 5, lane = tid & 31;
    const int row  = blockIdx.x * 8 + warp;
    const __half2* rh = (const __half2*)(hh + (size_t)row * H_);
    const __half2* rl = (const __half2*)(hl + (size_t)row * H_);
    float acc[E_] = {};
#pragma unroll
    for (int i = 0; i < H_ / 64; i++) {
        const int k2 = i * 32 + lane;
        const float2 fh = __half22float2(rh[k2]);
        const float2 fl = __half22float2(rl[k2]);
        const int k = 2 * k2;
        const float hv0 = fmaf(fh.x + fl.x, g_scale[k],     g_shift[k]);
        const float hv1 = fmaf(fh.y + fl.y, g_scale[k + 1], g_shift[k + 1]);
#pragma unroll
        for (int e = 0; e < E_; e++)
            acc[e] += hv0 * Wt[e * H_ + k] + hv1 * Wt[e * H_ + k + 1];
    }
#pragma unroll
    for (int e = 0; e < E_; e++)
#pragma unroll
        for (int off = 16; off; off >>= 1)
            acc[e] += __shfl_xor_sync(0xffffffffu, acc[e], off);
    if (lane == 0) {
        float best = acc[0] + b[0];
        int bi = 0;
#pragma unroll
        for (int e = 1; e < E_; e++) {
            const float v = acc[e] + b[e];
            if (v > best) { best = v; bi = e; }
        }
        g_act[row] = bi;
        atomicAdd(&g_cnt[bi], 1);
    }
}

__global__ void mlnn_scan()
{
    if (threadIdx.x == 0) {
        int s = 0;
#pragma unroll
        for (int e = 0; e < E_; e++) { g_off[e] = s; g_pos[e] = s; s += g_cnt[e]; }
    }
}

__global__ void mlnn_scatter()
{
    const int r = blockIdx.x * 256 + threadIdx.x;
    const int a = g_act[r];
    const int p = atomicAdd(&g_pos[a], 1);
    g_perm[p] = r;
}

// ---------------- launch ----------------
extern "C" void kernel_launch(void* const* d_in, const int* in_sizes, int n_in,
                              void* d_out, int out_size)
{
    const float* x     = (const float*)d_in[0];
    const float* dqn_W = (const float*)d_in[1];
    const float* dqn_b = (const float*)d_in[2];
    const float* Ws    = (const float*)d_in[3];
    const float* bs    = (const float*)d_in[4];
    const float* g0    = (const float*)d_in[5];
    const float* b0    = (const float*)d_in[6];
    const float* We    = (const float*)d_in[7];
    const float* be    = (const float*)d_in[8];
    const float* gmid  = (const float*)d_in[9];
    const float* bmid  = (const float*)d_in[10];
    const float* Wend  = (const float*)d_in[11];
    const float* bend  = (const float*)d_in[12];
    float* out = (float*)d_out;

    __half *xh, *xl, *ah, *al, *bh, *bl, *wh, *wl;
    float *scl, *shf, *bias2;
    cudaGetSymbolAddress((void**)&xh, g_xh);
    cudaGetSymbolAddress((void**)&xl, g_xl);
    cudaGetSymbolAddress((void**)&ah, g_ah);
    cudaGetSymbolAddress((void**)&al, g_al);
    cudaGetSymbolAddress((void**)&bh, g_bh);
    cudaGetSymbolAddress((void**)&bl, g_bl);
    cudaGetSymbolAddress((void**)&wh, g_wh);
    cudaGetSymbolAddress((void**)&wl, g_wl);
    cudaGetSymbolAddress((void**)&scl,   g_scale);
    cudaGetSymbolAddress((void**)&shf,   g_shift);
    cudaGetSymbolAddress((void**)&bias2, g_bias2);

    cudaFuncSetAttribute(mma_gemm<1024, false, true>,
                         cudaFuncAttributeMaxDynamicSharedMemorySize, SMEM_BYTES);
    cudaFuncSetAttribute(mma_gemm<512, true, true>,
                         cudaFuncAttributeMaxDynamicSharedMemorySize, SMEM_BYTES);
    cudaFuncSetAttribute(mma_gemm<512, false, false>,
                         cudaFuncAttributeMaxDynamicSharedMemorySize, SMEM_BYTES);

    // ---- input split + start-layer weight prep ----
    split_x<<<B_ * DIN_ / 1024, 256>>>(x, xh, xl);
    prep_w<DIN_><<<dim3(H_ / 32, 1), 256>>>(Ws, bs, nullptr, nullptr, wh, wl, bias2, H_);

    // ---- start layer: relu(x @ Ws + bs) -> hi/lo ----
    mma_gemm<1024, false, true><<<dim3(H_ / 128, B_ / 128), 256, SMEM_BYTES>>>(
        xh, xl, wh, wl, bias2, ah, al, nullptr, H_);
    mlnn_bn_stats<<<dim3(H_ / 64, 32), dim3(32, 8)>>>(ah, al);
    mlnn_bn_finalize<<<2, 256>>>(g0, b0);

    const __half* curh = ah; const __half* curl = al;
    __half* outs[2][2] = { { bh, bl }, { xh, xl } };   // mid outputs (xh/xl reused)
    for (int l = 0; l < NMID_; l++) {
        mlnn_routing<<<B_ / 8, 256>>>(curh, curl, dqn_W, dqn_b);
        mlnn_scan<<<1, 1>>>();
        mlnn_scatter<<<B_ / 256, 256>>>();
        prep_w<H_><<<dim3(H_ / 32, E_), 256>>>(
            We + (size_t)l * E_ * H_ * H_, be + (size_t)l * E_ * H_,
            scl, shf, wh, wl, bias2, H_);
        mma_gemm<512, true, true><<<dim3(H_ / 128, B_ / 128, E_), 256, SMEM_BYTES>>>(
            curh, curl, wh, wl, bias2, outs[l][0], outs[l][1], nullptr, H_);
        mlnn_bn_stats<<<dim3(H_ / 64, 32), dim3(32, 8)>>>(outs[l][0], outs[l][1]);
        mlnn_bn_finalize<<<2, 256>>>(gmid + (size_t)l * H_, bmid + (size_t)l * H_);
        curh = outs[l][0]; curl = outs[l][1];
    }

    // ---- end layer: relu(h @ Wend + bend) -> fp32 out ----
    prep_w<H_><<<dim3(DOUT_ / 32, 1), 256>>>(Wend, bend, scl, shf, wh, wl, bias2, DOUT_);
    mma_gemm<512, false, false><<<dim3(DOUT_ / 128, B_ / 128), 256, SMEM_BYTES>>>(
        curh, curl, wh, wl, bias2, nullptr, nullptr, out, DOUT_);
}

// round 14
// speedup vs baseline: 1.0760x; 1.0760x over previous
#include <cuda_runtime.h>
#include <cuda_fp16.h>
#include <cstdint>

#define B_    16384
#define DIN_  1024
#define H_    512
#define DOUT_ 256
#define E_    8
#define NMID_ 2
#define EPS_  1e-5f

// ---------------- scratch (device globals: no allocs allowed) ----------------
__device__ float g_h[B_ * H_];
__device__ float g_y[B_ * H_];
__device__ float g_psum[1024][H_];      // per-CTA-tile column partial sums
__device__ float g_psq[1024][H_];
__device__ float g_p2sum[16][H_];       // stage-2 partials
__device__ float g_p2sq[16][H_];
__device__ float g_scale[H_];
__device__ float g_shift[H_];
__device__ int   g_act[B_];
__device__ int   g_cnt[E_];
__device__ int   g_off[E_];
__device__ int   g_pos[E_];
__device__ int   g_perm[B_];

__device__ __forceinline__ void mma_f16(float* c, const uint32_t* a, const uint32_t* b) {
    asm volatile(
        "mma.sync.aligned.m16n8k16.row.col.f32.f16.f16.f32 "
        "{%0,%1,%2,%3}, {%4,%5,%6,%7}, {%8,%9}, {%0,%1,%2,%3};"
        : "+f"(c[0]), "+f"(c[1]), "+f"(c[2]), "+f"(c[3])
        : "r"(a[0]), "r"(a[1]), "r"(a[2]), "r"(a[3]), "r"(b[0]), "r"(b[1]));
}
__device__ __forceinline__ void ldsm4(uint32_t* r, uint32_t saddr) {
    asm volatile("ldmatrix.sync.aligned.m8n8.x4.shared.b16 {%0,%1,%2,%3}, [%4];"
                 : "=r"(r[0]), "=r"(r[1]), "=r"(r[2]), "=r"(r[3]) : "r"(saddr));
}

// SMEM (fp16): per buffer: Ah[128*40] Al[128*40] Bh[128*40] Bl[128*40]
#define PADH_    40                     // fp16 units per row (80 B stride)
#define ROWB_    (PADH_ * 2)            // 80 bytes
#define PART_B   (128 * ROWB_)          // 10240 B per part
#define BUFF_B   (4 * PART_B)           // 40960 B per buffer
#define SMEM_BYTES (2 * BUFF_B)         // 81920 B

// ============ 3xFP16-split mma.sync GEMM: C = relu(A @ W + bias) ============
// CTA tile 128x128, BK=32, 8 warps (2 m-groups x 4 n-groups), warp tile 64x32.
// A [*,KK] row-major (optional BN fuse + perm gather). W [KK,ldw] row-major.
// STATS: emit per-tile column sum/sumsq partials into g_psum/g_psq.
template<int KK, bool EXPERT, bool BN, bool STATS>
__global__ __launch_bounds__(256, 2) void mma_gemm(
    const float* __restrict__ A,
    const float* __restrict__ W, int ldw,
    const float* __restrict__ biasAll,
    const float* __restrict__ bnS, const float* __restrict__ bnB,
    float* __restrict__ C, int ldc)
{
    constexpr int NC = KK / 32;
    extern __shared__ __half smh[];

    const int tid  = threadIdx.x;
    const int wid  = tid >> 5;
    const int lane = tid & 31;
    const int gid  = lane >> 2;
    const int tig  = lane & 3;
    const int bm   = blockIdx.y * 128;
    const int bn0  = blockIdx.x * 128;
    const int slot = blockIdx.z * 128 + blockIdx.y;

    int cnt = B_, pbase = 0;
    const float* Wp   = W;
    const float* bias = biasAll;
    if (EXPERT) {
        const int e = blockIdx.z;
        cnt = g_cnt[e];
        if (bm >= cnt) {
            if (STATS) {
                for (int i = tid; i < 128; i += 256) {
                    g_psum[slot][bn0 + i] = 0.f;
                    g_psq[slot][bn0 + i]  = 0.f;
                }
            }
            return;
        }
        pbase = g_off[e];
        Wp    = W + (size_t)e * H_ * H_;
        bias  = biasAll + (size_t)e * H_;
    }

    // ---- fill assignments ----
    const int arow = tid >> 1, ahalf = tid & 1;
    int grow = bm + arow;
    if (EXPERT) {
        const int lr = bm + arow;
        grow = g_perm[pbase + (lr < cnt ? lr : cnt - 1)];
    }
    const float* Arow = A + (size_t)grow * KK + ahalf * 16;
    const int bkk = tid >> 3, bnl = tid & 7;

    float4 a4[4];
    float  bb[16];

    auto loadRegs = [&](int c) {
        const int k0 = c * 32;
        const float4* Ap = (const float4*)(Arow + k0);
#pragma unroll
        for (int j = 0; j < 4; j++) a4[j] = Ap[j];
        if (BN) {
            const float4* s4 = (const float4*)(bnS + k0 + ahalf * 16);
            const float4* t4 = (const float4*)(bnB + k0 + ahalf * 16);
#pragma unroll
            for (int j = 0; j < 4; j++) {
                float4 s = s4[j], t = t4[j];
                a4[j].x = fmaf(a4[j].x, s.x, t.x);
                a4[j].y = fmaf(a4[j].y, s.y, t.y);
                a4[j].z = fmaf(a4[j].z, s.z, t.z);
                a4[j].w = fmaf(a4[j].w, s.w, t.w);
            }
        }
        const float* Wk = Wp + (size_t)(k0 + bkk) * ldw + bn0 + bnl;
#pragma unroll
        for (int j = 0; j < 16; j++) bb[j] = __ldg(Wk + 8 * j);
    };

    auto stash = [&](int buf) {
        __half* Ah = smh + buf * (BUFF_B / 2);
        __half* Al = Ah + PART_B / 2;
        __half* Bh = Al + PART_B / 2;
        __half* Bl = Bh + PART_B / 2;
#pragma unroll
        for (int j = 0; j < 4; j++) {
            const float v[4] = { a4[j].x, a4[j].y, a4[j].z, a4[j].w };
            __half hi[4], lo[4];
#pragma unroll
            for (int q = 0; q < 4; q++) {
                hi[q] = __float2half_rn(v[q]);
                lo[q] = __float2half_rn(v[q] - __half2float(hi[q]));
            }
            const int o = arow * PADH_ + ahalf * 16 + j * 4;   // fp16 units, 8B aligned
            *(__half2*)(Ah + o)     = __halves2half2(hi[0], hi[1]);
            *(__half2*)(Ah + o + 2) = __halves2half2(hi[2], hi[3]);
            *(__half2*)(Al + o)     = __halves2half2(lo[0], lo[1]);
            *(__half2*)(Al + o + 2) = __halves2half2(lo[2], lo[3]);
        }
#pragma unroll
        for (int j = 0; j < 16; j++) {
            const int n = bnl + 8 * j;
            const __half hi = __float2half_rn(bb[j]);
            Bh[n * PADH_ + bkk] = hi;
            Bl[n * PADH_ + bkk] = __float2half_rn(bb[j] - __half2float(hi));
        }
    };

    // ---- accumulators ----
    float acc[4][4][4] = {};   // [mtile][ntile][frag]
    const int mbase = (wid & 1) * 64;
    const int nbase = (wid >> 1) * 32;

    const uint32_t sbase = (uint32_t)__cvta_generic_to_shared(smh);
    const uint32_t aLane = (uint32_t)((mbase + (lane & 15)) * ROWB_ + (lane >> 4) * 16);
    const uint32_t bLane = (uint32_t)((nbase + (((lane >> 3) >> 1) * 8) + (lane & 7)) * ROWB_
                                      + ((lane >> 3) & 1) * 16);

    auto domma = [&](int buf) {
        const uint32_t aH = sbase + buf * BUFF_B + aLane;
        const uint32_t aL = aH + PART_B;
        const uint32_t bH = sbase + buf * BUFF_B + 2 * PART_B + bLane;
        const uint32_t bL = bH + PART_B;
#pragma unroll
        for (int ks = 0; ks < 2; ks++) {
            uint32_t bh[2][4], bl[2][4];
#pragma unroll
            for (int ntp = 0; ntp < 2; ntp++) {
                const uint32_t off = (uint32_t)(ntp * 16 * ROWB_ + ks * 32);
                ldsm4(bh[ntp], bH + off);
                ldsm4(bl[ntp], bL + off);
            }
#pragma unroll
            for (int mt = 0; mt < 4; mt++) {
                uint32_t ah[4], al[4];
                const uint32_t off = (uint32_t)(mt * 16 * ROWB_ + ks * 32);
                ldsm4(ah, aH + off);
                ldsm4(al, aL + off);
#pragma unroll
                for (int nt = 0; nt < 4; nt++) {
                    const uint32_t* bhp = &bh[nt >> 1][(nt & 1) * 2];
                    const uint32_t* blp = &bl[nt >> 1][(nt & 1) * 2];
                    mma_f16(acc[mt][nt], ah, bhp);
                    mma_f16(acc[mt][nt], ah, blp);
                    mma_f16(acc[mt][nt], al, bhp);
                }
            }
        }
    };

    // ---- pipeline ----
    loadRegs(0);
    stash(0);
    __syncthreads();
    int buf = 0;
    for (int c = 0; c < NC; c++) {
        const bool more = (c + 1 < NC);
        if (more) loadRegs(c + 1);
        domma(buf);
        if (more) stash(buf ^ 1);
        __syncthreads();
        buf ^= 1;
    }

    // ---- epilogue: bias + relu (+ fused column stats) ----
    float cs[4][2], cq[4][2];
    if (STATS) {
#pragma unroll
        for (int nt = 0; nt < 4; nt++) {
            cs[nt][0] = cs[nt][1] = 0.f;
            cq[nt][0] = cq[nt][1] = 0.f;
        }
    }
#pragma unroll
    for (int mt = 0; mt < 4; mt++) {
#pragma unroll
        for (int half = 0; half < 2; half++) {
            const int lrow = mbase + mt * 16 + gid + half * 8;   // tile-local 0..127
            bool valid = true;
            int orow = bm + lrow;
            if (EXPERT) {
                valid = (bm + lrow) < cnt;
                orow  = valid ? g_perm[pbase + bm + lrow] : 0;
            }
            if (!valid) continue;
            float* Cr = C + (size_t)orow * ldc + bn0;
#pragma unroll
            for (int nt = 0; nt < 4; nt++) {
                const int n = nbase + nt * 8 + tig * 2;
                const float2 bv = *(const float2*)(bias + bn0 + n);
                float2 o;
                o.x = fmaxf(acc[mt][nt][half * 2 + 0] + bv.x, 0.f);
                o.y = fmaxf(acc[mt][nt][half * 2 + 1] + bv.y, 0.f);
                *(float2*)(Cr + n) = o;
                if (STATS) {
                    cs[nt][0] += o.x; cq[nt][0] += o.x * o.x;
                    cs[nt][1] += o.y; cq[nt][1] += o.y * o.y;
                }
            }
        }
    }

    if (STATS) {
        __shared__ float s_cs[128], s_cq[128];
        __syncthreads();                       // smem reuse barrier (stats arrays fresh)
        for (int i = tid; i < 128; i += 256) { s_cs[i] = 0.f; s_cq[i] = 0.f; }
        __syncthreads();
#pragma unroll
        for (int nt = 0; nt < 4; nt++) {
#pragma unroll
            for (int cc = 0; cc < 2; cc++) {
                float v = cs[nt][cc], w = cq[nt][cc];
#pragma unroll
                for (int mk = 4; mk <= 16; mk <<= 1) {
                    v += __shfl_xor_sync(0xffffffffu, v, mk);
                    w += __shfl_xor_sync(0xffffffffu, w, mk);
                }
                if (gid == 0) {
                    const int col = nbase + nt * 8 + tig * 2 + cc;   // tile-local
                    atomicAdd(&s_cs[col], v);    // exactly 2 adds/col: deterministic
                    atomicAdd(&s_cq[col], w);
                }
            }
        }
        __syncthreads();
        for (int i = tid; i < 128; i += 256) {
            g_psum[slot][bn0 + i] = s_cs[i];
            g_psq[slot][bn0 + i]  = s_cq[i];
        }
    }
}

// ---------------- stage-2 partial reduction: npart slots -> 16 ---------------
__global__ void bn_reduce(int npart)
{
    __shared__ float ss[8][33], sq[8][33];
    const int tx = threadIdx.x, ty = threadIdx.y;
    const int col = blockIdx.x * 32 + tx;
    const int per = npart >> 4;
    const int base = blockIdx.y * per;
    float s = 0.f, q = 0.f;
    for (int p = ty; p < per; p += 8) {
        s += g_psum[base + p][col];
        q += g_psq[base + p][col];
    }
    ss[ty][tx] = s; sq[ty][tx] = q;
    __syncthreads();
    if (ty == 0) {
#pragma unroll
        for (int y = 1; y < 8; y++) { s += ss[y][tx]; q += sq[y][tx]; }
        g_p2sum[blockIdx.y][col] = s;
        g_p2sq[blockIdx.y][col]  = q;
    }
}

__global__ void mlnn_bn_finalize(const float* __restrict__ gamma,
                                 const float* __restrict__ beta)
{
    const int c = blockIdx.x * 256 + threadIdx.x;
    float s = 0.f, q = 0.f;
#pragma unroll
    for (int p = 0; p < 16; p++) { s += g_p2sum[p][c]; q += g_p2sq[p][c]; }
    const float m   = s * (1.f / B_);
    const float var = q * (1.f / B_) - m * m;
    const float sc  = gamma[c] / sqrtf(var + EPS_);
    g_scale[c] = sc;
    g_shift[c] = beta[c] - m * sc;
    if (blockIdx.x == 0 && threadIdx.x < E_) g_cnt[threadIdx.x] = 0;
}

// ---------------- routing: warp per row, BN fused into load ----------------
__global__ __launch_bounds__(256)
void mlnn_routing(const float* __restrict__ h,
                  const float* __restrict__ W,    // [H,E]
                  const float* __restrict__ b)    // [E]
{
    __shared__ float Wt[E_ * H_];
    const int tid = threadIdx.x;
    for (int i = tid; i < H_ * E_; i += 256) {
        const int k = i >> 3, e = i & 7;
        Wt[e * H_ + k] = W[i];
    }
    __syncthreads();
    const int warp = tid >> 5, lane = tid & 31;
    const int row  = blockIdx.x * 8 + warp;
    const float* hr = h + (size_t)row * H_;
    float acc[E_] = {};
#pragma unroll
    for (int i = 0; i < H_ / 32; i++) {
        const int k = i * 32 + lane;
        const float hv = fmaf(hr[k], g_scale[k], g_shift[k]);
#pragma unroll
        for (int e = 0; e < E_; e++) acc[e] += hv * Wt[e * H_ + k];
    }
#pragma unroll
    for (int e = 0; e < E_; e++)
#pragma unroll
        for (int off = 16; off; off >>= 1)
            acc[e] += __shfl_xor_sync(0xffffffffu, acc[e], off);
    if (lane == 0) {
        float best = acc[0] + b[0];
        int bi = 0;
#pragma unroll
        for (int e = 1; e < E_; e++) {
            const float v = acc[e] + b[e];
            if (v > best) { best = v; bi = e; }
        }
        g_act[row] = bi;
        atomicAdd(&g_cnt[bi], 1);
    }
}

__global__ void mlnn_scan()
{
    if (threadIdx.x == 0) {
        int s = 0;
#pragma unroll
        for (int e = 0; e < E_; e++) { g_off[e] = s; g_pos[e] = s; s += g_cnt[e]; }
    }
}

__global__ void mlnn_scatter()
{
    const int r = blockIdx.x * 256 + threadIdx.x;
    const int a = g_act[r];
    const int p = atomicAdd(&g_pos[a], 1);
    g_perm[p] = r;
}

// ---------------- launch ----------------
extern "C" void kernel_launch(void* const* d_in, const int* in_sizes, int n_in,
                              void* d_out, int out_size)
{
    const float* x     = (const float*)d_in[0];
    const float* dqn_W = (const float*)d_in[1];
    const float* dqn_b = (const float*)d_in[2];
    const float* Ws    = (const float*)d_in[3];
    const float* bs    = (const float*)d_in[4];
    const float* g0    = (const float*)d_in[5];
    const float* b0    = (const float*)d_in[6];
    const float* We    = (const float*)d_in[7];
    const float* be    = (const float*)d_in[8];
    const float* gmid  = (const float*)d_in[9];
    const float* bmid  = (const float*)d_in[10];
    const float* Wend  = (const float*)d_in[11];
    const float* bend  = (const float*)d_in[12];
    float* out = (float*)d_out;

    float *h, *y, *scl, *shf;
    cudaGetSymbolAddress((void**)&h,   g_h);
    cudaGetSymbolAddress((void**)&y,   g_y);
    cudaGetSymbolAddress((void**)&scl, g_scale);
    cudaGetSymbolAddress((void**)&shf, g_shift);

    cudaFuncSetAttribute(mma_gemm<1024, false, false, true>,
                         cudaFuncAttributeMaxDynamicSharedMemorySize, SMEM_BYTES);
    cudaFuncSetAttribute(mma_gemm<512, true, true, true>,
                         cudaFuncAttributeMaxDynamicSharedMemorySize, SMEM_BYTES);
    cudaFuncSetAttribute(mma_gemm<512, false, true, false>,
                         cudaFuncAttributeMaxDynamicSharedMemorySize, SMEM_BYTES);

    // ---- start layer: h = relu(x @ Ws + bs); fused stats -> finalize ----
    mma_gemm<1024, false, false, true><<<dim3(H_ / 128, B_ / 128), 256, SMEM_BYTES>>>(
        x, Ws, H_, bs, nullptr, nullptr, h, H_);
    bn_reduce<<<dim3(H_ / 32, 16), dim3(32, 8)>>>(128);
    mlnn_bn_finalize<<<2, 256>>>(g0, b0);

    float* cur = h;
    float* nxt = y;
    for (int l = 0; l < NMID_; l++) {
        mlnn_routing<<<B_ / 8, 256>>>(cur, dqn_W, dqn_b);
        mlnn_scan<<<1, 1>>>();
        mlnn_scatter<<<B_ / 256, 256>>>();
        mma_gemm<512, true, true, true><<<dim3(H_ / 128, B_ / 128, E_), 256, SMEM_BYTES>>>(
            cur, We + (size_t)l * E_ * H_ * H_, H_,
            be + (size_t)l * E_ * H_, scl, shf, nxt, H_);
        bn_reduce<<<dim3(H_ / 32, 16), dim3(32, 8)>>>(1024);
        mlnn_bn_finalize<<<2, 256>>>(gmid + (size_t)l * H_, bmid + (size_t)l * H_);
        float* t = cur; cur = nxt; nxt = t;
    }

    // ---- end layer: out = relu(h @ Wend + bend), BN of last layer fused ----
    mma_gemm<512, false, true, false><<<dim3(DOUT_ / 128, B_ / 128), 256, SMEM_BYTES>>>(
        cur, Wend, DOUT_, bend, scl, shf, out, DOUT_);
}